// round 12
// baseline (speedup 1.0000x reference)
#include <cuda_runtime.h>
#include <cuda_fp16.h>
#include <math.h>

#define NHEADS 6
#define NTOK   343
#define DIMC   192
#define HD     32
#define NB     256
#define NWIN   64
#define MROWS  (NB*NTOK)      // 87808
#define QKVN   576
#define SCALEF 0.17677669529663687f

#define KSTRH  40    // attn K/Q smem stride (halves): 20 words %32 -> ldsm conflict-free
#define QSTRH  40
#define VTSTRH 360   // attn V^T smem stride (halves): 180 words %32==20 -> conflict-free
#define BMSTR  352   // bm row stride (floats)
#define XSTR   200   // gemm smem row stride (halves): 100 words %32==4 -> conflict-free

// ---- scratch (device globals; no runtime allocation) ----
__device__ __half g_q[(size_t)NB*NHEADS*NTOK*HD];
__device__ __half g_k[(size_t)NB*NHEADS*NTOK*HD];
__device__ __half g_v[(size_t)NB*NHEADS*NTOK*HD];
__device__ float  g_bm[(size_t)NWIN*NHEADS*NTOK*BMSTR];
__device__ __half g_ao[(size_t)NB*NTOK*DIMC];

__device__ __forceinline__ void mma_f16(float* c, const unsigned* a, unsigned b0, unsigned b1) {
    asm volatile(
        "mma.sync.aligned.m16n8k16.row.col.f32.f16.f16.f32 "
        "{%0,%1,%2,%3}, {%4,%5,%6,%7}, {%8,%9}, {%0,%1,%2,%3};"
        : "+f"(c[0]), "+f"(c[1]), "+f"(c[2]), "+f"(c[3])
        : "r"(a[0]), "r"(a[1]), "r"(a[2]), "r"(a[3]), "r"(b0), "r"(b1));
}

__device__ __forceinline__ void ldsm_x4(unsigned* r, unsigned addr) {
    asm volatile("ldmatrix.sync.aligned.m8n8.x4.shared.b16 {%0,%1,%2,%3}, [%4];"
        : "=r"(r[0]), "=r"(r[1]), "=r"(r[2]), "=r"(r[3]) : "r"(addr));
}

__device__ __forceinline__ unsigned smem_u32(const void* p) {
    return (unsigned)__cvta_generic_to_shared(p);
}

__device__ __forceinline__ unsigned pack_h2(float a, float b) {
    __half2 h = __floats2half2_rn(a, b);
    return *(unsigned*)&h;
}

// ---------------------------------------------------------------------------
// Kernel 1: fuse rpb gather + mask into g_bm[(w*6+h)][i][j], rows padded 352
// ---------------------------------------------------------------------------
__global__ void bm_kernel(const float* __restrict__ rpb, const float* __restrict__ mask)
{
    int i  = blockIdx.x;
    int wh = blockIdx.y;
    int w  = wh / NHEADS, h = wh - w * NHEADS;
    int di = i / 49, hi = (i / 7) % 7, wi = i % 7;
    float* dst = g_bm + ((size_t)wh * NTOK + i) * BMSTR;
    const float* mrow = mask + ((size_t)w * NTOK + i) * NTOK;
    for (int j = threadIdx.x; j < BMSTR; j += 128) {
        float val = 0.f;
        if (j < NTOK) {
            int dj = j / 49, hj = (j / 7) % 7, wj = j % 7;
            int idx = (di - dj + 6) * 169 + (hi - hj + 6) * 13 + (wi - wj + 6);
            val = rpb[idx * NHEADS + h] + mrow[j];
        }
        dst[j] = val;
    }
}

// ---------------------------------------------------------------------------
// Kernel 2: fp16-MMA QKV GEMM, ldmatrix fragment loads.
// ---------------------------------------------------------------------------
__global__ __launch_bounds__(256) void qkv_gemm_f16(const float* __restrict__ X,
                                                    const float* __restrict__ W,
                                                    const float* __restrict__ bias)
{
    extern __shared__ __half gs[];
    __half* Xs = gs;                 // 128 x XSTR
    __half* Ws = gs + 128 * XSTR;    // 64  x XSTR
    int tid = threadIdx.x, lane = tid & 31, warp = tid >> 5;
    int gid = lane >> 2, qd = lane & 3;
    int m0 = blockIdx.y * 128, n0 = blockIdx.x * 64;
    int mrow = (warp & 3) * 32, ncol = (warp >> 2) * 32;

    for (int idx = tid; idx < 128 * 48; idx += 256) {
        int r = idx / 48, c4 = idx % 48;
        float4 v = *(const float4*)&X[(size_t)(m0 + r) * DIMC + c4 * 4];
        *(__half2*)&Xs[r * XSTR + c4 * 4]     = __floats2half2_rn(v.x, v.y);
        *(__half2*)&Xs[r * XSTR + c4 * 4 + 2] = __floats2half2_rn(v.z, v.w);
    }
    for (int idx = tid; idx < 64 * 48; idx += 256) {
        int r = idx / 48, c4 = idx % 48;
        float4 v = *(const float4*)&W[(size_t)(n0 + r) * DIMC + c4 * 4];
        *(__half2*)&Ws[r * XSTR + c4 * 4]     = __floats2half2_rn(v.x, v.y);
        *(__half2*)&Ws[r * XSTR + c4 * 4 + 2] = __floats2half2_rn(v.z, v.w);
    }
    __syncthreads();

    // ldmatrix lane bases
    int r8 = lane & 7, g = lane >> 3;
    // A x4 order: (m0-7,k0)(m8-15,k0)(m0-7,k8)(m8-15,k8)
    unsigned aB0 = smem_u32(&Xs[(mrow + ((g & 1) << 3) + r8) * XSTR + ((g >> 1) << 3)]);
    unsigned aB1 = aB0 + 16 * XSTR * 2;
    // B x4 order: (nt0,k0)(nt0,k8)(nt1,k0)(nt1,k8)
    unsigned bB0 = smem_u32(&Ws[(ncol + ((g >> 1) << 3) + r8) * XSTR + ((g & 1) << 3)]);
    unsigned bB1 = bB0 + 16 * XSTR * 2;

    float c[2][4][4];
    #pragma unroll
    for (int mt = 0; mt < 2; mt++)
        #pragma unroll
        for (int nt = 0; nt < 4; nt++)
            #pragma unroll
            for (int i = 0; i < 4; i++) c[mt][nt][i] = 0.f;

    #pragma unroll
    for (int ks = 0; ks < 12; ks++) {
        unsigned koff = ks * 32;   // 16 halves * 2 bytes
        unsigned a0[4], a1[4], b0[4], b1[4];
        ldsm_x4(a0, aB0 + koff);
        ldsm_x4(a1, aB1 + koff);
        ldsm_x4(b0, bB0 + koff);
        ldsm_x4(b1, bB1 + koff);
        mma_f16(c[0][0], a0, b0[0], b0[1]);
        mma_f16(c[0][1], a0, b0[2], b0[3]);
        mma_f16(c[0][2], a0, b1[0], b1[1]);
        mma_f16(c[0][3], a0, b1[2], b1[3]);
        mma_f16(c[1][0], a1, b0[0], b0[1]);
        mma_f16(c[1][1], a1, b0[2], b0[3]);
        mma_f16(c[1][2], a1, b1[0], b1[1]);
        mma_f16(c[1][3], a1, b1[2], b1[3]);
    }

    #pragma unroll
    for (int mt = 0; mt < 2; mt++) {
        int gmA = m0 + mrow + mt * 16 + gid, gmB = gmA + 8;
        int bA = gmA / NTOK, tA = gmA - bA * NTOK;
        int bB = gmB / NTOK, tB = gmB - bB * NTOK;
        #pragma unroll
        for (int nt = 0; nt < 4; nt++) {
            int gn = n0 + ncol + nt * 8 + 2 * qd;
            int sec = gn / DIMC, rem = gn - sec * DIMC;
            int hh = rem >> 5, dd = rem & 31;
            float b0 = bias[gn], b1 = bias[gn + 1];
            float vA0 = c[mt][nt][0] + b0, vA1 = c[mt][nt][1] + b1;
            float vB0 = c[mt][nt][2] + b0, vB1 = c[mt][nt][3] + b1;
            size_t offA = (((size_t)bA * NHEADS + hh) * NTOK + tA) * HD + dd;
            size_t offB = (((size_t)bB * NHEADS + hh) * NTOK + tB) * HD + dd;
            if (sec == 0) {
                *(__half2*)&g_q[offA] = __floats2half2_rn(vA0 * SCALEF, vA1 * SCALEF);
                *(__half2*)&g_q[offB] = __floats2half2_rn(vB0 * SCALEF, vB1 * SCALEF);
            } else if (sec == 1) {
                *(__half2*)&g_k[offA] = __floats2half2_rn(vA0, vA1);
                *(__half2*)&g_k[offB] = __floats2half2_rn(vB0, vB1);
            } else {
                *(__half2*)&g_v[offA] = __floats2half2_rn(vA0, vA1);
                *(__half2*)&g_v[offB] = __floats2half2_rn(vB0, vB1);
            }
        }
    }
}

// ---------------------------------------------------------------------------
// Kernel 3: fp16 flash attention; ldmatrix K/V fragment loads.
// ---------------------------------------------------------------------------
template<bool MASK>
__device__ __forceinline__ void attn_pair(int pr,
                                          unsigned kAddr, unsigned vAddr,
                                          const float2 cur[4],
                                          const unsigned a[2][4], float occ[4][4],
                                          float& m0, float& m1, float& s0, float& s1,
                                          int qd)
{
    int kb0 = pr * 16;
    // K frags: x4 per sub covering k-chunks 0,8,16,24 (cols), rows kb0(+8)+r
    unsigned kA[4], kB[4];
    ldsm_x4(kA, kAddr + kb0 * (KSTRH * 2));
    ldsm_x4(kB, kAddr + (kb0 + 8) * (KSTRH * 2));

    float c[2][4];
    #pragma unroll
    for (int sub = 0; sub < 2; sub++) {
        c[sub][0] = c[sub][1] = c[sub][2] = c[sub][3] = 0.f;
        const unsigned* kf = sub ? kB : kA;
        mma_f16(c[sub], a[0], kf[0], kf[1]);
        mma_f16(c[sub], a[1], kf[2], kf[3]);
        float2 mA = cur[sub * 2];
        float2 mB = cur[sub * 2 + 1];
        c[sub][0] += mA.x; c[sub][1] += mA.y;
        c[sub][2] += mB.x; c[sub][3] += mB.y;
        if (MASK) {
            int k0 = kb0 + sub * 8 + 2 * qd;
            if (k0 >= NTOK)     { c[sub][0] = -1e30f; c[sub][2] = -1e30f; }
            if (k0 + 1 >= NTOK) { c[sub][1] = -1e30f; c[sub][3] = -1e30f; }
        }
    }
    float cm0 = fmaxf(fmaxf(c[0][0], c[0][1]), fmaxf(c[1][0], c[1][1]));
    float cm1 = fmaxf(fmaxf(c[0][2], c[0][3]), fmaxf(c[1][2], c[1][3]));
    cm0 = fmaxf(cm0, __shfl_xor_sync(0xffffffffu, cm0, 1));
    cm0 = fmaxf(cm0, __shfl_xor_sync(0xffffffffu, cm0, 2));
    cm1 = fmaxf(cm1, __shfl_xor_sync(0xffffffffu, cm1, 1));
    cm1 = fmaxf(cm1, __shfl_xor_sync(0xffffffffu, cm1, 2));
    float mn0 = fmaxf(m0, cm0), mn1 = fmaxf(m1, cm1);
    float sc0 = __expf(m0 - mn0), sc1 = __expf(m1 - mn1);
    m0 = mn0; m1 = mn1;
    s0 *= sc0; s1 *= sc1;
    #pragma unroll
    for (int nh = 0; nh < 4; nh++) {
        occ[nh][0] *= sc0; occ[nh][1] *= sc0;
        occ[nh][2] *= sc1; occ[nh][3] *= sc1;
    }
    float e00 = __expf(c[0][0] - m0), e01 = __expf(c[0][1] - m0);
    float e02 = __expf(c[0][2] - m1), e03 = __expf(c[0][3] - m1);
    float e10 = __expf(c[1][0] - m0), e11 = __expf(c[1][1] - m0);
    float e12 = __expf(c[1][2] - m1), e13 = __expf(c[1][3] - m1);
    s0 += e00 + e01 + e10 + e11;
    s1 += e02 + e03 + e12 + e13;
    unsigned pa[4];
    pa[0] = pack_h2(e00, e01);
    pa[1] = pack_h2(e02, e03);
    pa[2] = pack_h2(e10, e11);
    pa[3] = pack_h2(e12, e13);
    // V frags: x4 #1 = (nh0,k0)(nh0,k8)(nh1,k0)(nh1,k8); #2 = nh2,nh3
    unsigned v0[4], v1[4];
    ldsm_x4(v0, vAddr + kb0 * 2);
    ldsm_x4(v1, vAddr + kb0 * 2 + 16 * (VTSTRH * 2));
    mma_f16(occ[0], pa, v0[0], v0[1]);
    mma_f16(occ[1], pa, v0[2], v0[3]);
    mma_f16(occ[2], pa, v1[0], v1[1]);
    mma_f16(occ[3], pa, v1[2], v1[3]);
}

__global__ __launch_bounds__(512, 2) void attn_tc()
{
    extern __shared__ __half smh[];
    __half* Ks = smh;                      // 352*40 [key][hd]
    __half* Vt = Ks + 352 * KSTRH;         // 32*360 [hd][key]
    __half* Qs = Vt + 32 * VTSTRH;         // 352*40 [q][hd]

    int tid  = threadIdx.x;
    int h    = blockIdx.x;
    int by   = blockIdx.y;
    int b    = ((by & 3) << 6) | (by >> 2);    // L2-locality remap
    int w    = b & (NWIN - 1);
    int lane = tid & 31, warp = tid >> 5;
    int gid  = lane >> 2, qd = lane & 3;

    size_t base = (((size_t)b * NHEADS) + h) * NTOK * HD;
    const __half* qg = g_q + base;
    const __half* kg = g_k + base;
    const __half* vg = g_v + base;
    const float*  bm = g_bm + (size_t)(w * NHEADS + h) * NTOK * BMSTR;

    __half2 zero2 = __floats2half2_rn(0.f, 0.f);
    for (int i = tid; i < 352 * 16; i += 512) {
        int j = i >> 4, d2 = (i & 15) * 2;
        __half2 kv = zero2, vv = zero2;
        if (j < NTOK) {
            kv = *(const __half2*)&kg[j * HD + d2];
            vv = *(const __half2*)&vg[j * HD + d2];
        }
        *(__half2*)&Ks[j * KSTRH + d2] = kv;
        Vt[d2 * VTSTRH + j]       = __low2half(vv);
        Vt[(d2 + 1) * VTSTRH + j] = __high2half(vv);
        int t = j > NTOK - 1 ? NTOK - 1 : j;
        *(__half2*)&Qs[j * QSTRH + d2] = *(const __half2*)&qg[t * HD + d2];
    }
    __syncthreads();

    // ldmatrix lane bases (row-relative; constant across wt)
    int r8 = lane & 7, g = lane >> 3;
    unsigned kAddr = smem_u32(&Ks[r8 * KSTRH + (g << 3)]);           // rows r8, col g*8
    unsigned vAddr = smem_u32(&Vt[(((g >> 1) << 3) + r8) * VTSTRH + ((g & 1) << 3)]);

    for (int wt = warp; wt < 22; wt += 16) {
        int r0 = wt * 16 + gid, r1 = r0 + 8;
        int tA = r0 > NTOK - 1 ? NTOK - 1 : r0;
        int tB = r1 > NTOK - 1 ? NTOK - 1 : r1;

        unsigned a[2][4];
        #pragma unroll
        for (int ks = 0; ks < 2; ks++) {
            a[ks][0] = *(const unsigned*)&Qs[r0 * QSTRH + ks * 16 + 2 * qd];
            a[ks][1] = *(const unsigned*)&Qs[r1 * QSTRH + ks * 16 + 2 * qd];
            a[ks][2] = *(const unsigned*)&Qs[r0 * QSTRH + ks * 16 + 8 + 2 * qd];
            a[ks][3] = *(const unsigned*)&Qs[r1 * QSTRH + ks * 16 + 8 + 2 * qd];
        }
        float occ[4][4];
        #pragma unroll
        for (int nh = 0; nh < 4; nh++)
            #pragma unroll
            for (int i = 0; i < 4; i++) occ[nh][i] = 0.f;
        float m0 = -1e30f, m1 = -1e30f, s0 = 0.f, s1 = 0.f;

        const float* bmA = bm + (size_t)tA * BMSTR + 2 * qd;
        const float* bmB = bm + (size_t)tB * BMSTR + 2 * qd;

        float2 pf[4];
        pf[0] = *(const float2*)&bmA[0];
        pf[1] = *(const float2*)&bmB[0];
        pf[2] = *(const float2*)&bmA[8];
        pf[3] = *(const float2*)&bmB[8];

        #pragma unroll 1
        for (int pr = 0; pr < 21; pr++) {
            float2 cur[4] = { pf[0], pf[1], pf[2], pf[3] };
            int nk = (pr + 1) * 16;
            pf[0] = *(const float2*)&bmA[nk];
            pf[1] = *(const float2*)&bmB[nk];
            pf[2] = *(const float2*)&bmA[nk + 8];
            pf[3] = *(const float2*)&bmB[nk + 8];
            attn_pair<false>(pr, kAddr, vAddr, cur, a, occ, m0, m1, s0, s1, qd);
        }
        attn_pair<true>(21, kAddr, vAddr, pf, a, occ, m0, m1, s0, s1, qd);

        s0 += __shfl_xor_sync(0xffffffffu, s0, 1);
        s0 += __shfl_xor_sync(0xffffffffu, s0, 2);
        s1 += __shfl_xor_sync(0xffffffffu, s1, 1);
        s1 += __shfl_xor_sync(0xffffffffu, s1, 2);
        float i0 = 1.f / s0, i1 = 1.f / s1;

        #pragma unroll
        for (int nh = 0; nh < 4; nh++) {
            int col = h * HD + nh * 8 + 2 * qd;
            if (r0 < NTOK)
                *(__half2*)&g_ao[((size_t)b * NTOK + r0) * DIMC + col] =
                    __floats2half2_rn(occ[nh][0] * i0, occ[nh][1] * i0);
            if (r1 < NTOK)
                *(__half2*)&g_ao[((size_t)b * NTOK + r1) * DIMC + col] =
                    __floats2half2_rn(occ[nh][2] * i1, occ[nh][3] * i1);
        }
    }
}

// ---------------------------------------------------------------------------
// Kernel 4: fp16-MMA projection GEMM, ldmatrix fragment loads.
// ---------------------------------------------------------------------------
__global__ __launch_bounds__(256) void proj_gemm_f16(const float* __restrict__ W,
                                                     const float* __restrict__ bias,
                                                     float* __restrict__ out)
{
    extern __shared__ __half gs[];
    __half* As = gs;                 // 128 x XSTR
    __half* Ws = gs + 128 * XSTR;    // 64  x XSTR
    int tid = threadIdx.x, lane = tid & 31, warp = tid >> 5;
    int gid = lane >> 2, qd = lane & 3;
    int m0 = blockIdx.y * 128, n0 = blockIdx.x * 64;
    int mrow = (warp & 3) * 32, ncol = (warp >> 2) * 32;

    for (int idx = tid; idx < 128 * 48; idx += 256) {
        int r = idx / 48, c4 = idx % 48;
        uint2 v = *(const uint2*)&g_ao[(size_t)(m0 + r) * DIMC + c4 * 4];
        *(uint2*)&As[r * XSTR + c4 * 4] = v;
    }
    for (int idx = tid; idx < 64 * 48; idx += 256) {
        int r = idx / 48, c4 = idx % 48;
        float4 v = *(const float4*)&W[(size_t)(n0 + r) * DIMC + c4 * 4];
        *(__half2*)&Ws[r * XSTR + c4 * 4]     = __floats2half2_rn(v.x, v.y);
        *(__half2*)&Ws[r * XSTR + c4 * 4 + 2] = __floats2half2_rn(v.z, v.w);
    }
    __syncthreads();

    int r8 = lane & 7, g = lane >> 3;
    unsigned aB0 = smem_u32(&As[(mrow + ((g & 1) << 3) + r8) * XSTR + ((g >> 1) << 3)]);
    unsigned aB1 = aB0 + 16 * XSTR * 2;
    unsigned bB0 = smem_u32(&Ws[(ncol + ((g >> 1) << 3) + r8) * XSTR + ((g & 1) << 3)]);
    unsigned bB1 = bB0 + 16 * XSTR * 2;

    float c[2][4][4];
    #pragma unroll
    for (int mt = 0; mt < 2; mt++)
        #pragma unroll
        for (int nt = 0; nt < 4; nt++)
            #pragma unroll
            for (int i = 0; i < 4; i++) c[mt][nt][i] = 0.f;

    #pragma unroll
    for (int ks = 0; ks < 12; ks++) {
        unsigned koff = ks * 32;
        unsigned a0[4], a1[4], b0[4], b1[4];
        ldsm_x4(a0, aB0 + koff);
        ldsm_x4(a1, aB1 + koff);
        ldsm_x4(b0, bB0 + koff);
        ldsm_x4(b1, bB1 + koff);
        mma_f16(c[0][0], a0, b0[0], b0[1]);
        mma_f16(c[0][1], a0, b0[2], b0[3]);
        mma_f16(c[0][2], a0, b1[0], b1[1]);
        mma_f16(c[0][3], a0, b1[2], b1[3]);
        mma_f16(c[1][0], a1, b0[0], b0[1]);
        mma_f16(c[1][1], a1, b0[2], b0[3]);
        mma_f16(c[1][2], a1, b1[0], b1[1]);
        mma_f16(c[1][3], a1, b1[2], b1[3]);
    }

    #pragma unroll
    for (int mt = 0; mt < 2; mt++) {
        int gmA = m0 + mrow + mt * 16 + gid, gmB = gmA + 8;
        #pragma unroll
        for (int nt = 0; nt < 4; nt++) {
            int gn = n0 + ncol + nt * 8 + 2 * qd;
            float b0 = bias[gn], b1 = bias[gn + 1];
            *(float2*)&out[(size_t)gmA * DIMC + gn] =
                make_float2(c[mt][nt][0] + b0, c[mt][nt][1] + b1);
            *(float2*)&out[(size_t)gmB * DIMC + gn] =
                make_float2(c[mt][nt][2] + b0, c[mt][nt][3] + b1);
        }
    }
}

// ---------------------------------------------------------------------------
extern "C" void kernel_launch(void* const* d_in, const int* in_sizes, int n_in,
                              void* d_out, int out_size)
{
    const float* x      = (const float*)d_in[0];
    const float* mask   = (const float*)d_in[1];
    const float* qkv_w  = (const float*)d_in[2];
    const float* qkv_b  = (const float*)d_in[3];
    const float* rpb    = (const float*)d_in[4];
    const float* proj_w = (const float*)d_in[5];
    const float* proj_b = (const float*)d_in[6];
    float* out = (float*)d_out;

    (void)in_sizes; (void)n_in; (void)out_size;

    int smem_attn = (352 * KSTRH + 32 * VTSTRH + 352 * QSTRH) * (int)sizeof(__half);
    int smem_gemm = 192 * XSTR * (int)sizeof(__half);
    cudaFuncSetAttribute(attn_tc, cudaFuncAttributeMaxDynamicSharedMemorySize, smem_attn);
    cudaFuncSetAttribute(qkv_gemm_f16, cudaFuncAttributeMaxDynamicSharedMemorySize, smem_gemm);
    cudaFuncSetAttribute(proj_gemm_f16, cudaFuncAttributeMaxDynamicSharedMemorySize, smem_gemm);

    bm_kernel<<<dim3(NTOK, NWIN * NHEADS), 128>>>(rpb, mask);
    qkv_gemm_f16<<<dim3(QKVN / 64, MROWS / 128), 256, smem_gemm>>>(x, qkv_w, qkv_b);
    attn_tc<<<dim3(NHEADS, NB), 512, smem_attn>>>();
    proj_gemm_f16<<<dim3(DIMC / 64, MROWS / 128), 256, smem_gemm>>>(proj_w, proj_b, out);
}

// round 13
// speedup vs baseline: 1.3964x; 1.3964x over previous
#include <cuda_runtime.h>
#include <cuda_fp16.h>
#include <math.h>

#define NHEADS 6
#define NTOK   343
#define DIMC   192
#define HD     32
#define NB     256
#define NWIN   64
#define MROWS  (NB*NTOK)      // 87808
#define QKVN   576
#define SCALEF 0.17677669529663687f

#define KSTRH  40    // attn K/Q smem stride (halves)
#define QSTRH  40
#define VTSTRH 360   // attn V^T smem stride (halves)
#define BMSTR  352   // bm row stride (floats)
#define XSTR   200   // gemm smem row stride (halves)

// ---- scratch (device globals; no runtime allocation) ----
__device__ __half g_q[(size_t)NB*NHEADS*NTOK*HD];
__device__ __half g_k[(size_t)NB*NHEADS*NTOK*HD];
__device__ __half g_v[(size_t)NB*NHEADS*NTOK*HD];
__device__ float  g_bm[(size_t)NWIN*NHEADS*NTOK*BMSTR];
__device__ __half g_ao[(size_t)NB*NTOK*DIMC];
__device__ __half g_xh[(size_t)MROWS*DIMC];   // fp16 X (33.7MB, L2-resident)
__device__ __half g_wh[(size_t)QKVN*DIMC];    // fp16 qkv W

__device__ __forceinline__ void mma_f16(float* c, const unsigned* a, unsigned b0, unsigned b1) {
    asm volatile(
        "mma.sync.aligned.m16n8k16.row.col.f32.f16.f16.f32 "
        "{%0,%1,%2,%3}, {%4,%5,%6,%7}, {%8,%9}, {%0,%1,%2,%3};"
        : "+f"(c[0]), "+f"(c[1]), "+f"(c[2]), "+f"(c[3])
        : "r"(a[0]), "r"(a[1]), "r"(a[2]), "r"(a[3]), "r"(b0), "r"(b1));
}

__device__ __forceinline__ unsigned pack_h2(float a, float b) {
    __half2 h = __floats2half2_rn(a, b);
    return *(unsigned*)&h;
}

// ---------------------------------------------------------------------------
// Kernel 0a/0b: convert X and qkv W to fp16 (same rounding qkv used in-block)
// ---------------------------------------------------------------------------
__global__ void cvt_x(const float* __restrict__ X)
{
    size_t i = ((size_t)blockIdx.x * blockDim.x + threadIdx.x) * 4;
    if (i < (size_t)MROWS * DIMC) {
        float4 v = *(const float4*)&X[i];
        *(__half2*)&g_xh[i]     = __floats2half2_rn(v.x, v.y);
        *(__half2*)&g_xh[i + 2] = __floats2half2_rn(v.z, v.w);
    }
}
__global__ void cvt_w(const float* __restrict__ W)
{
    size_t i = ((size_t)blockIdx.x * blockDim.x + threadIdx.x) * 4;
    if (i < (size_t)QKVN * DIMC) {
        float4 v = *(const float4*)&W[i];
        *(__half2*)&g_wh[i]     = __floats2half2_rn(v.x, v.y);
        *(__half2*)&g_wh[i + 2] = __floats2half2_rn(v.z, v.w);
    }
}

// ---------------------------------------------------------------------------
// Kernel 1: fuse rpb gather + mask into g_bm[(w*6+h)][i][j], rows padded 352
// ---------------------------------------------------------------------------
__global__ void bm_kernel(const float* __restrict__ rpb, const float* __restrict__ mask)
{
    int i  = blockIdx.x;
    int wh = blockIdx.y;
    int w  = wh / NHEADS, h = wh - w * NHEADS;
    int di = i / 49, hi = (i / 7) % 7, wi = i % 7;
    float* dst = g_bm + ((size_t)wh * NTOK + i) * BMSTR;
    const float* mrow = mask + ((size_t)w * NTOK + i) * NTOK;
    for (int j = threadIdx.x; j < BMSTR; j += 128) {
        float val = 0.f;
        if (j < NTOK) {
            int dj = j / 49, hj = (j / 7) % 7, wj = j % 7;
            int idx = (di - dj + 6) * 169 + (hi - hj + 6) * 13 + (wi - wj + 6);
            val = rpb[idx * NHEADS + h] + mrow[j];
        }
        dst[j] = val;
    }
}

// ---------------------------------------------------------------------------
// Kernel 2: fp16-MMA QKV GEMM reading pre-converted fp16 X/W (L2-resident).
// ---------------------------------------------------------------------------
__global__ __launch_bounds__(256) void qkv_gemm_f16(const float* __restrict__ bias)
{
    extern __shared__ __half gs[];
    __half* Xs = gs;                 // 128 x XSTR
    __half* Ws = gs + 128 * XSTR;    // 64  x XSTR
    int tid = threadIdx.x, lane = tid & 31, warp = tid >> 5;
    int gid = lane >> 2, qd = lane & 3;
    int m0 = blockIdx.y * 128, n0 = blockIdx.x * 64;
    int mrow = (warp & 3) * 32, ncol = (warp >> 2) * 32;

    for (int idx = tid; idx < 128 * 24; idx += 256) {
        int r = idx / 24, c = idx % 24;
        *(uint4*)&Xs[r * XSTR + c * 8] = *(const uint4*)&g_xh[(size_t)(m0 + r) * DIMC + c * 8];
    }
    for (int idx = tid; idx < 64 * 24; idx += 256) {
        int r = idx / 24, c = idx % 24;
        *(uint4*)&Ws[r * XSTR + c * 8] = *(const uint4*)&g_wh[(size_t)(n0 + r) * DIMC + c * 8];
    }
    __syncthreads();

    float c[2][4][4];
    #pragma unroll
    for (int mt = 0; mt < 2; mt++)
        #pragma unroll
        for (int nt = 0; nt < 4; nt++)
            #pragma unroll
            for (int i = 0; i < 4; i++) c[mt][nt][i] = 0.f;

    #pragma unroll
    for (int ks = 0; ks < 12; ks++) {
        int kk = ks * 16;
        unsigned a[2][4], bf[4][2];
        #pragma unroll
        for (int mt = 0; mt < 2; mt++) {
            int r = mrow + mt * 16 + gid;
            a[mt][0] = *(const unsigned*)&Xs[r * XSTR + kk + 2 * qd];
            a[mt][1] = *(const unsigned*)&Xs[(r + 8) * XSTR + kk + 2 * qd];
            a[mt][2] = *(const unsigned*)&Xs[r * XSTR + kk + 8 + 2 * qd];
            a[mt][3] = *(const unsigned*)&Xs[(r + 8) * XSTR + kk + 8 + 2 * qd];
        }
        #pragma unroll
        for (int nt = 0; nt < 4; nt++) {
            int rn = ncol + nt * 8 + gid;
            bf[nt][0] = *(const unsigned*)&Ws[rn * XSTR + kk + 2 * qd];
            bf[nt][1] = *(const unsigned*)&Ws[rn * XSTR + kk + 8 + 2 * qd];
        }
        #pragma unroll
        for (int mt = 0; mt < 2; mt++)
            #pragma unroll
            for (int nt = 0; nt < 4; nt++)
                mma_f16(c[mt][nt], a[mt], bf[nt][0], bf[nt][1]);
    }

    #pragma unroll
    for (int mt = 0; mt < 2; mt++) {
        int gmA = m0 + mrow + mt * 16 + gid, gmB = gmA + 8;
        int bA = gmA / NTOK, tA = gmA - bA * NTOK;
        int bB = gmB / NTOK, tB = gmB - bB * NTOK;
        #pragma unroll
        for (int nt = 0; nt < 4; nt++) {
            int gn = n0 + ncol + nt * 8 + 2 * qd;
            int sec = gn / DIMC, rem = gn - sec * DIMC;
            int hh = rem >> 5, dd = rem & 31;
            float b0 = bias[gn], b1 = bias[gn + 1];
            float vA0 = c[mt][nt][0] + b0, vA1 = c[mt][nt][1] + b1;
            float vB0 = c[mt][nt][2] + b0, vB1 = c[mt][nt][3] + b1;
            size_t offA = (((size_t)bA * NHEADS + hh) * NTOK + tA) * HD + dd;
            size_t offB = (((size_t)bB * NHEADS + hh) * NTOK + tB) * HD + dd;
            if (sec == 0) {
                *(__half2*)&g_q[offA] = __floats2half2_rn(vA0 * SCALEF, vA1 * SCALEF);
                *(__half2*)&g_q[offB] = __floats2half2_rn(vB0 * SCALEF, vB1 * SCALEF);
            } else if (sec == 1) {
                *(__half2*)&g_k[offA] = __floats2half2_rn(vA0, vA1);
                *(__half2*)&g_k[offB] = __floats2half2_rn(vB0, vB1);
            } else {
                *(__half2*)&g_v[offA] = __floats2half2_rn(vA0, vA1);
                *(__half2*)&g_v[offB] = __floats2half2_rn(vB0, vB1);
            }
        }
    }
}

// ---------------------------------------------------------------------------
// Kernel 3: fp16 register-resident flash attention, 2 blocks/SM (round-11).
// ---------------------------------------------------------------------------
template<bool MASK>
__device__ __forceinline__ void attn_pair(int pr, int gid, int qd,
                                          const __half* __restrict__ Ks,
                                          const __half* __restrict__ Vt,
                                          const float2 cur[4],
                                          const unsigned a[2][4], float occ[4][4],
                                          float& m0, float& m1, float& s0, float& s1)
{
    int kb0 = pr * 16;
    float c[2][4];
    #pragma unroll
    for (int sub = 0; sub < 2; sub++) {
        c[sub][0] = c[sub][1] = c[sub][2] = c[sub][3] = 0.f;
        int kb = kb0 + sub * 8;
        const __half* krow = &Ks[(kb + gid) * KSTRH + 2 * qd];
        #pragma unroll
        for (int ks = 0; ks < 2; ks++) {
            unsigned b0 = *(const unsigned*)&krow[ks * 16];
            unsigned b1 = *(const unsigned*)&krow[ks * 16 + 8];
            mma_f16(c[sub], a[ks], b0, b1);
        }
        float2 mA = cur[sub * 2];
        float2 mB = cur[sub * 2 + 1];
        c[sub][0] += mA.x; c[sub][1] += mA.y;
        c[sub][2] += mB.x; c[sub][3] += mB.y;
        if (MASK) {
            int k0 = kb + 2 * qd;
            if (k0 >= NTOK)     { c[sub][0] = -1e30f; c[sub][2] = -1e30f; }
            if (k0 + 1 >= NTOK) { c[sub][1] = -1e30f; c[sub][3] = -1e30f; }
        }
    }
    float cm0 = fmaxf(fmaxf(c[0][0], c[0][1]), fmaxf(c[1][0], c[1][1]));
    float cm1 = fmaxf(fmaxf(c[0][2], c[0][3]), fmaxf(c[1][2], c[1][3]));
    cm0 = fmaxf(cm0, __shfl_xor_sync(0xffffffffu, cm0, 1));
    cm0 = fmaxf(cm0, __shfl_xor_sync(0xffffffffu, cm0, 2));
    cm1 = fmaxf(cm1, __shfl_xor_sync(0xffffffffu, cm1, 1));
    cm1 = fmaxf(cm1, __shfl_xor_sync(0xffffffffu, cm1, 2));
    float mn0 = fmaxf(m0, cm0), mn1 = fmaxf(m1, cm1);
    float sc0 = __expf(m0 - mn0), sc1 = __expf(m1 - mn1);
    m0 = mn0; m1 = mn1;
    s0 *= sc0; s1 *= sc1;
    #pragma unroll
    for (int nh = 0; nh < 4; nh++) {
        occ[nh][0] *= sc0; occ[nh][1] *= sc0;
        occ[nh][2] *= sc1; occ[nh][3] *= sc1;
    }
    float e00 = __expf(c[0][0] - m0), e01 = __expf(c[0][1] - m0);
    float e02 = __expf(c[0][2] - m1), e03 = __expf(c[0][3] - m1);
    float e10 = __expf(c[1][0] - m0), e11 = __expf(c[1][1] - m0);
    float e12 = __expf(c[1][2] - m1), e13 = __expf(c[1][3] - m1);
    s0 += e00 + e01 + e10 + e11;
    s1 += e02 + e03 + e12 + e13;
    unsigned pa[4];
    pa[0] = pack_h2(e00, e01);
    pa[1] = pack_h2(e02, e03);
    pa[2] = pack_h2(e10, e11);
    pa[3] = pack_h2(e12, e13);
    #pragma unroll
    for (int nh = 0; nh < 4; nh++) {
        const __half* vrow = &Vt[(nh * 8 + gid) * VTSTRH + kb0 + 2 * qd];
        unsigned b0 = *(const unsigned*)&vrow[0];
        unsigned b1 = *(const unsigned*)&vrow[8];
        mma_f16(occ[nh], pa, b0, b1);
    }
}

__global__ __launch_bounds__(512, 2) void attn_tc()
{
    extern __shared__ __half smh[];
    __half* Ks = smh;                      // 352*40 [key][hd]
    __half* Vt = Ks + 352 * KSTRH;         // 32*360 [hd][key]
    __half* Qs = Vt + 32 * VTSTRH;         // 352*40 [q][hd]

    int tid  = threadIdx.x;
    int h    = blockIdx.x;
    int by   = blockIdx.y;
    int b    = ((by & 3) << 6) | (by >> 2);    // L2-locality remap
    int w    = b & (NWIN - 1);
    int lane = tid & 31, warp = tid >> 5;
    int gid  = lane >> 2, qd = lane & 3;

    size_t base = (((size_t)b * NHEADS) + h) * NTOK * HD;
    const __half* qg = g_q + base;
    const __half* kg = g_k + base;
    const __half* vg = g_v + base;
    const float*  bm = g_bm + (size_t)(w * NHEADS + h) * NTOK * BMSTR;

    __half2 zero2 = __floats2half2_rn(0.f, 0.f);
    for (int i = tid; i < 352 * 16; i += 512) {
        int j = i >> 4, d2 = (i & 15) * 2;
        __half2 kv = zero2, vv = zero2;
        if (j < NTOK) {
            kv = *(const __half2*)&kg[j * HD + d2];
            vv = *(const __half2*)&vg[j * HD + d2];
        }
        *(__half2*)&Ks[j * KSTRH + d2] = kv;
        Vt[d2 * VTSTRH + j]       = __low2half(vv);
        Vt[(d2 + 1) * VTSTRH + j] = __high2half(vv);
        int t = j > NTOK - 1 ? NTOK - 1 : j;
        *(__half2*)&Qs[j * QSTRH + d2] = *(const __half2*)&qg[t * HD + d2];
    }
    __syncthreads();

    for (int wt = warp; wt < 22; wt += 16) {
        int r0 = wt * 16 + gid, r1 = r0 + 8;
        int tA = r0 > NTOK - 1 ? NTOK - 1 : r0;
        int tB = r1 > NTOK - 1 ? NTOK - 1 : r1;

        unsigned a[2][4];
        #pragma unroll
        for (int ks = 0; ks < 2; ks++) {
            a[ks][0] = *(const unsigned*)&Qs[r0 * QSTRH + ks * 16 + 2 * qd];
            a[ks][1] = *(const unsigned*)&Qs[r1 * QSTRH + ks * 16 + 2 * qd];
            a[ks][2] = *(const unsigned*)&Qs[r0 * QSTRH + ks * 16 + 8 + 2 * qd];
            a[ks][3] = *(const unsigned*)&Qs[r1 * QSTRH + ks * 16 + 8 + 2 * qd];
        }
        float occ[4][4];
        #pragma unroll
        for (int nh = 0; nh < 4; nh++)
            #pragma unroll
            for (int i = 0; i < 4; i++) occ[nh][i] = 0.f;
        float m0 = -1e30f, m1 = -1e30f, s0 = 0.f, s1 = 0.f;

        const float* bmA = bm + (size_t)tA * BMSTR + 2 * qd;
        const float* bmB = bm + (size_t)tB * BMSTR + 2 * qd;

        float2 pf[4];
        pf[0] = *(const float2*)&bmA[0];
        pf[1] = *(const float2*)&bmB[0];
        pf[2] = *(const float2*)&bmA[8];
        pf[3] = *(const float2*)&bmB[8];

        #pragma unroll 1
        for (int pr = 0; pr < 21; pr++) {
            float2 cur[4] = { pf[0], pf[1], pf[2], pf[3] };
            int nk = (pr + 1) * 16;
            pf[0] = *(const float2*)&bmA[nk];
            pf[1] = *(const float2*)&bmB[nk];
            pf[2] = *(const float2*)&bmA[nk + 8];
            pf[3] = *(const float2*)&bmB[nk + 8];
            attn_pair<false>(pr, gid, qd, Ks, Vt, cur, a, occ, m0, m1, s0, s1);
        }
        attn_pair<true>(21, gid, qd, Ks, Vt, pf, a, occ, m0, m1, s0, s1);

        s0 += __shfl_xor_sync(0xffffffffu, s0, 1);
        s0 += __shfl_xor_sync(0xffffffffu, s0, 2);
        s1 += __shfl_xor_sync(0xffffffffu, s1, 1);
        s1 += __shfl_xor_sync(0xffffffffu, s1, 2);
        float i0 = 1.f / s0, i1 = 1.f / s1;

        #pragma unroll
        for (int nh = 0; nh < 4; nh++) {
            int col = h * HD + nh * 8 + 2 * qd;
            if (r0 < NTOK)
                *(__half2*)&g_ao[((size_t)b * NTOK + r0) * DIMC + col] =
                    __floats2half2_rn(occ[nh][0] * i0, occ[nh][1] * i0);
            if (r1 < NTOK)
                *(__half2*)&g_ao[((size_t)b * NTOK + r1) * DIMC + col] =
                    __floats2half2_rn(occ[nh][2] * i1, occ[nh][3] * i1);
        }
    }
}

// ---------------------------------------------------------------------------
// Kernel 4: fp16-MMA projection GEMM (round-11 scalar-LDS version).
// ---------------------------------------------------------------------------
__global__ __launch_bounds__(256) void proj_gemm_f16(const float* __restrict__ W,
                                                     const float* __restrict__ bias,
                                                     float* __restrict__ out)
{
    extern __shared__ __half gs[];
    __half* As = gs;                 // 128 x XSTR
    __half* Ws = gs + 128 * XSTR;    // 64  x XSTR
    int tid = threadIdx.x, lane = tid & 31, warp = tid >> 5;
    int gid = lane >> 2, qd = lane & 3;
    int m0 = blockIdx.y * 128, n0 = blockIdx.x * 64;
    int mrow = (warp & 3) * 32, ncol = (warp >> 2) * 32;

    for (int idx = tid; idx < 128 * 48; idx += 256) {
        int r = idx / 48, c4 = idx % 48;
        uint2 v = *(const uint2*)&g_ao[(size_t)(m0 + r) * DIMC + c4 * 4];
        *(uint2*)&As[r * XSTR + c4 * 4] = v;
    }
    for (int idx = tid; idx < 64 * 48; idx += 256) {
        int r = idx / 48, c4 = idx % 48;
        float4 v = *(const float4*)&W[(size_t)(n0 + r) * DIMC + c4 * 4];
        *(__half2*)&Ws[r * XSTR + c4 * 4]     = __floats2half2_rn(v.x, v.y);
        *(__half2*)&Ws[r * XSTR + c4 * 4 + 2] = __floats2half2_rn(v.z, v.w);
    }
    __syncthreads();

    float c[2][4][4];
    #pragma unroll
    for (int mt = 0; mt < 2; mt++)
        #pragma unroll
        for (int nt = 0; nt < 4; nt++)
            #pragma unroll
            for (int i = 0; i < 4; i++) c[mt][nt][i] = 0.f;

    #pragma unroll
    for (int ks = 0; ks < 12; ks++) {
        int kk = ks * 16;
        unsigned a[2][4], bf[4][2];
        #pragma unroll
        for (int mt = 0; mt < 2; mt++) {
            int r = mrow + mt * 16 + gid;
            a[mt][0] = *(const unsigned*)&As[r * XSTR + kk + 2 * qd];
            a[mt][1] = *(const unsigned*)&As[(r + 8) * XSTR + kk + 2 * qd];
            a[mt][2] = *(const unsigned*)&As[r * XSTR + kk + 8 + 2 * qd];
            a[mt][3] = *(const unsigned*)&As[(r + 8) * XSTR + kk + 8 + 2 * qd];
        }
        #pragma unroll
        for (int nt = 0; nt < 4; nt++) {
            int rn = ncol + nt * 8 + gid;
            bf[nt][0] = *(const unsigned*)&Ws[rn * XSTR + kk + 2 * qd];
            bf[nt][1] = *(const unsigned*)&Ws[rn * XSTR + kk + 8 + 2 * qd];
        }
        #pragma unroll
        for (int mt = 0; mt < 2; mt++)
            #pragma unroll
            for (int nt = 0; nt < 4; nt++)
                mma_f16(c[mt][nt], a[mt], bf[nt][0], bf[nt][1]);
    }

    #pragma unroll
    for (int mt = 0; mt < 2; mt++) {
        int gmA = m0 + mrow + mt * 16 + gid, gmB = gmA + 8;
        #pragma unroll
        for (int nt = 0; nt < 4; nt++) {
            int gn = n0 + ncol + nt * 8 + 2 * qd;
            float b0 = bias[gn], b1 = bias[gn + 1];
            *(float2*)&out[(size_t)gmA * DIMC + gn] =
                make_float2(c[mt][nt][0] + b0, c[mt][nt][1] + b1);
            *(float2*)&out[(size_t)gmB * DIMC + gn] =
                make_float2(c[mt][nt][2] + b0, c[mt][nt][3] + b1);
        }
    }
}

// ---------------------------------------------------------------------------
extern "C" void kernel_launch(void* const* d_in, const int* in_sizes, int n_in,
                              void* d_out, int out_size)
{
    const float* x      = (const float*)d_in[0];
    const float* mask   = (const float*)d_in[1];
    const float* qkv_w  = (const float*)d_in[2];
    const float* qkv_b  = (const float*)d_in[3];
    const float* rpb    = (const float*)d_in[4];
    const float* proj_w = (const float*)d_in[5];
    const float* proj_b = (const float*)d_in[6];
    float* out = (float*)d_out;

    (void)in_sizes; (void)n_in; (void)out_size;

    int smem_attn = (352 * KSTRH + 32 * VTSTRH + 352 * QSTRH) * (int)sizeof(__half);
    int smem_gemm = 192 * XSTR * (int)sizeof(__half);
    cudaFuncSetAttribute(attn_tc, cudaFuncAttributeMaxDynamicSharedMemorySize, smem_attn);
    cudaFuncSetAttribute(qkv_gemm_f16, cudaFuncAttributeMaxDynamicSharedMemorySize, smem_gemm);
    cudaFuncSetAttribute(proj_gemm_f16, cudaFuncAttributeMaxDynamicSharedMemorySize, smem_gemm);

    cvt_x<<<(MROWS * DIMC / 4 + 255) / 256, 256>>>(x);
    cvt_w<<<(QKVN * DIMC / 4 + 255) / 256, 256>>>(qkv_w);
    bm_kernel<<<dim3(NTOK, NWIN * NHEADS), 128>>>(rpb, mask);
    qkv_gemm_f16<<<dim3(QKVN / 64, MROWS / 128), 256, smem_gemm>>>(qkv_b);
    attn_tc<<<dim3(NHEADS, NB), 512, smem_attn>>>();
    proj_gemm_f16<<<dim3(DIMC / 64, MROWS / 128), 256, smem_gemm>>>(proj_w, proj_b, out);
}

// round 14
// speedup vs baseline: 1.4636x; 1.0481x over previous
#include <cuda_runtime.h>
#include <cuda_fp16.h>
#include <math.h>

#define NHEADS 6
#define NTOK   343
#define DIMC   192
#define HD     32
#define NB     256
#define NWIN   64
#define MROWS  (NB*NTOK)      // 87808
#define QKVN   576
#define SCALEF 0.17677669529663687f
#define LOG2E  1.4426950408889634f
#define QSC    (SCALEF * LOG2E)

#define KSTRH  40    // attn K/Q smem stride (halves)
#define QSTRH  40
#define VTSTRH 360   // attn V^T smem stride (halves)
#define BMSTR  352   // bm row stride (floats)
#define XSTR   200   // gemm smem row stride (halves)

// ---- scratch (device globals; no runtime allocation) ----
__device__ __half g_q[(size_t)NB*NHEADS*NTOK*HD];
__device__ __half g_k[(size_t)NB*NHEADS*NTOK*HD];
__device__ __half g_v[(size_t)NB*NHEADS*NTOK*HD];
__device__ float  g_bm[(size_t)NWIN*NHEADS*NTOK*BMSTR];   // (bias+mask)*log2e
__device__ __half g_ao[(size_t)NB*NTOK*DIMC];

__device__ __forceinline__ void mma_f16(float* c, const unsigned* a, unsigned b0, unsigned b1) {
    asm volatile(
        "mma.sync.aligned.m16n8k16.row.col.f32.f16.f16.f32 "
        "{%0,%1,%2,%3}, {%4,%5,%6,%7}, {%8,%9}, {%0,%1,%2,%3};"
        : "+f"(c[0]), "+f"(c[1]), "+f"(c[2]), "+f"(c[3])
        : "r"(a[0]), "r"(a[1]), "r"(a[2]), "r"(a[3]), "r"(b0), "r"(b1));
}

// 2^x on fp32 MUFU
__device__ __forceinline__ float ex2f(float x) {
    float r;
    asm("ex2.approx.ftz.f32 %0, %1;" : "=f"(r) : "f"(x));
    return r;
}

// pack two f32 args, 2^x on both halves in ONE MUFU op
__device__ __forceinline__ unsigned ex2h2(float a, float b) {
    __half2 h = __floats2half2_rn(a, b);
    unsigned p = *(unsigned*)&h, r;
    asm("ex2.approx.f16x2 %0, %1;" : "=r"(r) : "r"(p));
    return r;
}

// ---------------------------------------------------------------------------
// Kernel 1: bm[(w*6+h)][i][j] = (bias+mask)*log2e, rows padded 352
// ---------------------------------------------------------------------------
__global__ void bm_kernel(const float* __restrict__ rpb, const float* __restrict__ mask)
{
    int i  = blockIdx.x;
    int wh = blockIdx.y;
    int w  = wh / NHEADS, h = wh - w * NHEADS;
    int di = i / 49, hi = (i / 7) % 7, wi = i % 7;
    float* dst = g_bm + ((size_t)wh * NTOK + i) * BMSTR;
    const float* mrow = mask + ((size_t)w * NTOK + i) * NTOK;
    for (int j = threadIdx.x; j < BMSTR; j += 128) {
        float val = 0.f;
        if (j < NTOK) {
            int dj = j / 49, hj = (j / 7) % 7, wj = j % 7;
            int idx = (di - dj + 6) * 169 + (hi - hj + 6) * 13 + (wi - wj + 6);
            val = (rpb[idx * NHEADS + h] + mrow[j]) * LOG2E;
        }
        dst[j] = val;
    }
}

// ---------------------------------------------------------------------------
// Kernel 2: fp16-MMA QKV GEMM (round-11 form); q scaled by SCALEF*log2e
// ---------------------------------------------------------------------------
__global__ __launch_bounds__(256) void qkv_gemm_f16(const float* __restrict__ X,
                                                    const float* __restrict__ W,
                                                    const float* __restrict__ bias)
{
    extern __shared__ __half gs[];
    __half* Xs = gs;                 // 128 x XSTR
    __half* Ws = gs + 128 * XSTR;    // 64  x XSTR
    int tid = threadIdx.x, lane = tid & 31, warp = tid >> 5;
    int gid = lane >> 2, qd = lane & 3;
    int m0 = blockIdx.y * 128, n0 = blockIdx.x * 64;
    int mrow = (warp & 3) * 32, ncol = (warp >> 2) * 32;

    for (int idx = tid; idx < 128 * 48; idx += 256) {
        int r = idx / 48, c4 = idx % 48;
        float4 v = *(const float4*)&X[(size_t)(m0 + r) * DIMC + c4 * 4];
        *(__half2*)&Xs[r * XSTR + c4 * 4]     = __floats2half2_rn(v.x, v.y);
        *(__half2*)&Xs[r * XSTR + c4 * 4 + 2] = __floats2half2_rn(v.z, v.w);
    }
    for (int idx = tid; idx < 64 * 48; idx += 256) {
        int r = idx / 48, c4 = idx % 48;
        float4 v = *(const float4*)&W[(size_t)(n0 + r) * DIMC + c4 * 4];
        *(__half2*)&Ws[r * XSTR + c4 * 4]     = __floats2half2_rn(v.x, v.y);
        *(__half2*)&Ws[r * XSTR + c4 * 4 + 2] = __floats2half2_rn(v.z, v.w);
    }
    __syncthreads();

    float c[2][4][4];
    #pragma unroll
    for (int mt = 0; mt < 2; mt++)
        #pragma unroll
        for (int nt = 0; nt < 4; nt++)
            #pragma unroll
            for (int i = 0; i < 4; i++) c[mt][nt][i] = 0.f;

    #pragma unroll
    for (int ks = 0; ks < 12; ks++) {
        int kk = ks * 16;
        unsigned a[2][4], bf[4][2];
        #pragma unroll
        for (int mt = 0; mt < 2; mt++) {
            int r = mrow + mt * 16 + gid;
            a[mt][0] = *(const unsigned*)&Xs[r * XSTR + kk + 2 * qd];
            a[mt][1] = *(const unsigned*)&Xs[(r + 8) * XSTR + kk + 2 * qd];
            a[mt][2] = *(const unsigned*)&Xs[r * XSTR + kk + 8 + 2 * qd];
            a[mt][3] = *(const unsigned*)&Xs[(r + 8) * XSTR + kk + 8 + 2 * qd];
        }
        #pragma unroll
        for (int nt = 0; nt < 4; nt++) {
            int rn = ncol + nt * 8 + gid;
            bf[nt][0] = *(const unsigned*)&Ws[rn * XSTR + kk + 2 * qd];
            bf[nt][1] = *(const unsigned*)&Ws[rn * XSTR + kk + 8 + 2 * qd];
        }
        #pragma unroll
        for (int mt = 0; mt < 2; mt++)
            #pragma unroll
            for (int nt = 0; nt < 4; nt++)
                mma_f16(c[mt][nt], a[mt], bf[nt][0], bf[nt][1]);
    }

    #pragma unroll
    for (int mt = 0; mt < 2; mt++) {
        int gmA = m0 + mrow + mt * 16 + gid, gmB = gmA + 8;
        int bA = gmA / NTOK, tA = gmA - bA * NTOK;
        int bB = gmB / NTOK, tB = gmB - bB * NTOK;
        #pragma unroll
        for (int nt = 0; nt < 4; nt++) {
            int gn = n0 + ncol + nt * 8 + 2 * qd;
            int sec = gn / DIMC, rem = gn - sec * DIMC;
            int hh = rem >> 5, dd = rem & 31;
            float b0 = bias[gn], b1 = bias[gn + 1];
            float vA0 = c[mt][nt][0] + b0, vA1 = c[mt][nt][1] + b1;
            float vB0 = c[mt][nt][2] + b0, vB1 = c[mt][nt][3] + b1;
            size_t offA = (((size_t)bA * NHEADS + hh) * NTOK + tA) * HD + dd;
            size_t offB = (((size_t)bB * NHEADS + hh) * NTOK + tB) * HD + dd;
            if (sec == 0) {
                *(__half2*)&g_q[offA] = __floats2half2_rn(vA0 * QSC, vA1 * QSC);
                *(__half2*)&g_q[offB] = __floats2half2_rn(vB0 * QSC, vB1 * QSC);
            } else if (sec == 1) {
                *(__half2*)&g_k[offA] = __floats2half2_rn(vA0, vA1);
                *(__half2*)&g_k[offB] = __floats2half2_rn(vB0, vB1);
            } else {
                *(__half2*)&g_v[offA] = __floats2half2_rn(vA0, vA1);
                *(__half2*)&g_v[offB] = __floats2half2_rn(vB0, vB1);
            }
        }
    }
}

// ---------------------------------------------------------------------------
// Kernel 3: fp16 flash attention; log2-domain softmax, f16x2 EX2.
// ---------------------------------------------------------------------------
template<bool MASK>
__device__ __forceinline__ void attn_pair(int pr, int gid, int qd,
                                          const __half* __restrict__ Ks,
                                          const __half* __restrict__ Vt,
                                          const float2 cur[4],
                                          const unsigned a[2][4], float occ[4][4],
                                          float& m0, float& m1, float& s0, float& s1)
{
    int kb0 = pr * 16;
    float c[2][4];
    #pragma unroll
    for (int sub = 0; sub < 2; sub++) {
        c[sub][0] = c[sub][1] = c[sub][2] = c[sub][3] = 0.f;
        int kb = kb0 + sub * 8;
        const __half* krow = &Ks[(kb + gid) * KSTRH + 2 * qd];
        #pragma unroll
        for (int ks = 0; ks < 2; ks++) {
            unsigned b0 = *(const unsigned*)&krow[ks * 16];
            unsigned b1 = *(const unsigned*)&krow[ks * 16 + 8];
            mma_f16(c[sub], a[ks], b0, b1);
        }
        float2 mA = cur[sub * 2];
        float2 mB = cur[sub * 2 + 1];
        c[sub][0] += mA.x; c[sub][1] += mA.y;
        c[sub][2] += mB.x; c[sub][3] += mB.y;
        if (MASK) {
            int k0 = kb + 2 * qd;
            if (k0 >= NTOK)     { c[sub][0] = -1e30f; c[sub][2] = -1e30f; }
            if (k0 + 1 >= NTOK) { c[sub][1] = -1e30f; c[sub][3] = -1e30f; }
        }
    }
    float cm0 = fmaxf(fmaxf(c[0][0], c[0][1]), fmaxf(c[1][0], c[1][1]));
    float cm1 = fmaxf(fmaxf(c[0][2], c[0][3]), fmaxf(c[1][2], c[1][3]));
    cm0 = fmaxf(cm0, __shfl_xor_sync(0xffffffffu, cm0, 1));
    cm0 = fmaxf(cm0, __shfl_xor_sync(0xffffffffu, cm0, 2));
    cm1 = fmaxf(cm1, __shfl_xor_sync(0xffffffffu, cm1, 1));
    cm1 = fmaxf(cm1, __shfl_xor_sync(0xffffffffu, cm1, 2));
    float mn0 = fmaxf(m0, cm0), mn1 = fmaxf(m1, cm1);
    float sc0 = ex2f(m0 - mn0), sc1 = ex2f(m1 - mn1);
    m0 = mn0; m1 = mn1;
    s0 *= sc0; s1 *= sc1;
    #pragma unroll
    for (int nh = 0; nh < 4; nh++) {
        occ[nh][0] *= sc0; occ[nh][1] *= sc0;
        occ[nh][2] *= sc1; occ[nh][3] *= sc1;
    }
    // P = 2^(c-m) via f16x2 MUFU (one op per score pair)
    unsigned pa[4];
    pa[0] = ex2h2(c[0][0] - m0, c[0][1] - m0);
    pa[1] = ex2h2(c[0][2] - m1, c[0][3] - m1);
    pa[2] = ex2h2(c[1][0] - m0, c[1][1] - m0);
    pa[3] = ex2h2(c[1][2] - m1, c[1][3] - m1);
    // accumulate row sums from the SAME fp16 values fed to the mma
    float2 f0 = __half22float2(*(__half2*)&pa[0]);
    float2 f2 = __half22float2(*(__half2*)&pa[2]);
    s0 += (f0.x + f0.y) + (f2.x + f2.y);
    float2 f1 = __half22float2(*(__half2*)&pa[1]);
    float2 f3 = __half22float2(*(__half2*)&pa[3]);
    s1 += (f1.x + f1.y) + (f3.x + f3.y);
    #pragma unroll
    for (int nh = 0; nh < 4; nh++) {
        const __half* vrow = &Vt[(nh * 8 + gid) * VTSTRH + kb0 + 2 * qd];
        unsigned b0 = *(const unsigned*)&vrow[0];
        unsigned b1 = *(const unsigned*)&vrow[8];
        mma_f16(occ[nh], pa, b0, b1);
    }
}

__global__ __launch_bounds__(512, 2) void attn_tc()
{
    extern __shared__ __half smh[];
    __half* Ks = smh;                      // 352*40 [key][hd]
    __half* Vt = Ks + 352 * KSTRH;         // 32*360 [hd][key]
    __half* Qs = Vt + 32 * VTSTRH;         // 352*40 [q][hd]

    int tid  = threadIdx.x;
    int h    = blockIdx.x;
    int by   = blockIdx.y;
    int b    = ((by & 3) << 6) | (by >> 2);    // L2-locality remap
    int w    = b & (NWIN - 1);
    int lane = tid & 31, warp = tid >> 5;
    int gid  = lane >> 2, qd = lane & 3;

    size_t base = (((size_t)b * NHEADS) + h) * NTOK * HD;
    const __half* qg = g_q + base;
    const __half* kg = g_k + base;
    const __half* vg = g_v + base;
    const float*  bm = g_bm + (size_t)(w * NHEADS + h) * NTOK * BMSTR;

    __half2 zero2 = __floats2half2_rn(0.f, 0.f);
    for (int i = tid; i < 352 * 16; i += 512) {
        int j = i >> 4, d2 = (i & 15) * 2;
        __half2 kv = zero2, vv = zero2;
        if (j < NTOK) {
            kv = *(const __half2*)&kg[j * HD + d2];
            vv = *(const __half2*)&vg[j * HD + d2];
        }
        *(__half2*)&Ks[j * KSTRH + d2] = kv;
        Vt[d2 * VTSTRH + j]       = __low2half(vv);
        Vt[(d2 + 1) * VTSTRH + j] = __high2half(vv);
        int t = j > NTOK - 1 ? NTOK - 1 : j;
        *(__half2*)&Qs[j * QSTRH + d2] = *(const __half2*)&qg[t * HD + d2];
    }
    __syncthreads();

    for (int wt = warp; wt < 22; wt += 16) {
        int r0 = wt * 16 + gid, r1 = r0 + 8;
        int tA = r0 > NTOK - 1 ? NTOK - 1 : r0;
        int tB = r1 > NTOK - 1 ? NTOK - 1 : r1;

        unsigned a[2][4];
        #pragma unroll
        for (int ks = 0; ks < 2; ks++) {
            a[ks][0] = *(const unsigned*)&Qs[r0 * QSTRH + ks * 16 + 2 * qd];
            a[ks][1] = *(const unsigned*)&Qs[r1 * QSTRH + ks * 16 + 2 * qd];
            a[ks][2] = *(const unsigned*)&Qs[r0 * QSTRH + ks * 16 + 8 + 2 * qd];
            a[ks][3] = *(const unsigned*)&Qs[r1 * QSTRH + ks * 16 + 8 + 2 * qd];
        }
        float occ[4][4];
        #pragma unroll
        for (int nh = 0; nh < 4; nh++)
            #pragma unroll
            for (int i = 0; i < 4; i++) occ[nh][i] = 0.f;
        float m0 = -1e30f, m1 = -1e30f, s0 = 0.f, s1 = 0.f;

        const float* bmA = bm + (size_t)tA * BMSTR + 2 * qd;
        const float* bmB = bm + (size_t)tB * BMSTR + 2 * qd;

        float2 pf[4];
        pf[0] = *(const float2*)&bmA[0];
        pf[1] = *(const float2*)&bmB[0];
        pf[2] = *(const float2*)&bmA[8];
        pf[3] = *(const float2*)&bmB[8];

        #pragma unroll 1
        for (int pr = 0; pr < 21; pr++) {
            float2 cur[4] = { pf[0], pf[1], pf[2], pf[3] };
            int nk = (pr + 1) * 16;
            pf[0] = *(const float2*)&bmA[nk];
            pf[1] = *(const float2*)&bmB[nk];
            pf[2] = *(const float2*)&bmA[nk + 8];
            pf[3] = *(const float2*)&bmB[nk + 8];
            attn_pair<false>(pr, gid, qd, Ks, Vt, cur, a, occ, m0, m1, s0, s1);
        }
        attn_pair<true>(21, gid, qd, Ks, Vt, pf, a, occ, m0, m1, s0, s1);

        s0 += __shfl_xor_sync(0xffffffffu, s0, 1);
        s0 += __shfl_xor_sync(0xffffffffu, s0, 2);
        s1 += __shfl_xor_sync(0xffffffffu, s1, 1);
        s1 += __shfl_xor_sync(0xffffffffu, s1, 2);
        float i0 = 1.f / s0, i1 = 1.f / s1;

        #pragma unroll
        for (int nh = 0; nh < 4; nh++) {
            int col = h * HD + nh * 8 + 2 * qd;
            if (r0 < NTOK)
                *(__half2*)&g_ao[((size_t)b * NTOK + r0) * DIMC + col] =
                    __floats2half2_rn(occ[nh][0] * i0, occ[nh][1] * i0);
            if (r1 < NTOK)
                *(__half2*)&g_ao[((size_t)b * NTOK + r1) * DIMC + col] =
                    __floats2half2_rn(occ[nh][2] * i1, occ[nh][3] * i1);
        }
    }
}

// ---------------------------------------------------------------------------
// Kernel 4: fp16-MMA projection GEMM (round-11 scalar-LDS version).
// ---------------------------------------------------------------------------
__global__ __launch_bounds__(256) void proj_gemm_f16(const float* __restrict__ W,
                                                     const float* __restrict__ bias,
                                                     float* __restrict__ out)
{
    extern __shared__ __half gs[];
    __half* As = gs;                 // 128 x XSTR
    __half* Ws = gs + 128 * XSTR;    // 64  x XSTR
    int tid = threadIdx.x, lane = tid & 31, warp = tid >> 5;
    int gid = lane >> 2, qd = lane & 3;
    int m0 = blockIdx.y * 128, n0 = blockIdx.x * 64;
    int mrow = (warp & 3) * 32, ncol = (warp >> 2) * 32;

    for (int idx = tid; idx < 128 * 48; idx += 256) {
        int r = idx / 48, c4 = idx % 48;
        uint2 v = *(const uint2*)&g_ao[(size_t)(m0 + r) * DIMC + c4 * 4];
        *(uint2*)&As[r * XSTR + c4 * 4] = v;
    }
    for (int idx = tid; idx < 64 * 48; idx += 256) {
        int r = idx / 48, c4 = idx % 48;
        float4 v = *(const float4*)&W[(size_t)(n0 + r) * DIMC + c4 * 4];
        *(__half2*)&Ws[r * XSTR + c4 * 4]     = __floats2half2_rn(v.x, v.y);
        *(__half2*)&Ws[r * XSTR + c4 * 4 + 2] = __floats2half2_rn(v.z, v.w);
    }
    __syncthreads();

    float c[2][4][4];
    #pragma unroll
    for (int mt = 0; mt < 2; mt++)
        #pragma unroll
        for (int nt = 0; nt < 4; nt++)
            #pragma unroll
            for (int i = 0; i < 4; i++) c[mt][nt][i] = 0.f;

    #pragma unroll
    for (int ks = 0; ks < 12; ks++) {
        int kk = ks * 16;
        unsigned a[2][4], bf[4][2];
        #pragma unroll
        for (int mt = 0; mt < 2; mt++) {
            int r = mrow + mt * 16 + gid;
            a[mt][0] = *(const unsigned*)&As[r * XSTR + kk + 2 * qd];
            a[mt][1] = *(const unsigned*)&As[(r + 8) * XSTR + kk + 2 * qd];
            a[mt][2] = *(const unsigned*)&As[r * XSTR + kk + 8 + 2 * qd];
            a[mt][3] = *(const unsigned*)&As[(r + 8) * XSTR + kk + 8 + 2 * qd];
        }
        #pragma unroll
        for (int nt = 0; nt < 4; nt++) {
            int rn = ncol + nt * 8 + gid;
            bf[nt][0] = *(const unsigned*)&Ws[rn * XSTR + kk + 2 * qd];
            bf[nt][1] = *(const unsigned*)&Ws[rn * XSTR + kk + 8 + 2 * qd];
        }
        #pragma unroll
        for (int mt = 0; mt < 2; mt++)
            #pragma unroll
            for (int nt = 0; nt < 4; nt++)
                mma_f16(c[mt][nt], a[mt], bf[nt][0], bf[nt][1]);
    }

    #pragma unroll
    for (int mt = 0; mt < 2; mt++) {
        int gmA = m0 + mrow + mt * 16 + gid, gmB = gmA + 8;
        #pragma unroll
        for (int nt = 0; nt < 4; nt++) {
            int gn = n0 + ncol + nt * 8 + 2 * qd;
            float b0 = bias[gn], b1 = bias[gn + 1];
            *(float2*)&out[(size_t)gmA * DIMC + gn] =
                make_float2(c[mt][nt][0] + b0, c[mt][nt][1] + b1);
            *(float2*)&out[(size_t)gmB * DIMC + gn] =
                make_float2(c[mt][nt][2] + b0, c[mt][nt][3] + b1);
        }
    }
}

// ---------------------------------------------------------------------------
extern "C" void kernel_launch(void* const* d_in, const int* in_sizes, int n_in,
                              void* d_out, int out_size)
{
    const float* x      = (const float*)d_in[0];
    const float* mask   = (const float*)d_in[1];
    const float* qkv_w  = (const float*)d_in[2];
    const float* qkv_b  = (const float*)d_in[3];
    const float* rpb    = (const float*)d_in[4];
    const float* proj_w = (const float*)d_in[5];
    const float* proj_b = (const float*)d_in[6];
    float* out = (float*)d_out;

    (void)in_sizes; (void)n_in; (void)out_size;

    int smem_attn = (352 * KSTRH + 32 * VTSTRH + 352 * QSTRH) * (int)sizeof(__half);
    int smem_gemm = 192 * XSTR * (int)sizeof(__half);
    cudaFuncSetAttribute(attn_tc, cudaFuncAttributeMaxDynamicSharedMemorySize, smem_attn);
    cudaFuncSetAttribute(qkv_gemm_f16, cudaFuncAttributeMaxDynamicSharedMemorySize, smem_gemm);
    cudaFuncSetAttribute(proj_gemm_f16, cudaFuncAttributeMaxDynamicSharedMemorySize, smem_gemm);

    bm_kernel<<<dim3(NTOK, NWIN * NHEADS), 128>>>(rpb, mask);
    qkv_gemm_f16<<<dim3(QKVN / 64, MROWS / 128), 256, smem_gemm>>>(x, qkv_w, qkv_b);
    attn_tc<<<dim3(NHEADS, NB), 512, smem_attn>>>();
    proj_gemm_f16<<<dim3(DIMC / 64, MROWS / 128), 256, smem_gemm>>>(proj_w, proj_b, out);
}

// round 15
// speedup vs baseline: 1.5034x; 1.0272x over previous
#include <cuda_runtime.h>
#include <cuda_fp16.h>
#include <math.h>

#define NHEADS 6
#define NTOK   343
#define DIMC   192
#define HD     32
#define NB     256
#define NWIN   64
#define MROWS  (NB*NTOK)      // 87808
#define QKVN   576
#define SCALEF 0.17677669529663687f
#define LOG2E  1.4426950408889634f
#define QSC    (SCALEF * LOG2E)
#define SLACK  3.0f

#define KSTRH  40    // attn K/Q smem stride (halves)
#define QSTRH  40
#define VTSTRH 360   // attn V^T smem stride (halves)
#define BMSTR  352   // bm row stride (halves)
#define XSTR   200   // gemm smem row stride (halves)

// ---- scratch (device globals; no runtime allocation) ----
__device__ __half g_q[(size_t)NB*NHEADS*NTOK*HD];
__device__ __half g_k[(size_t)NB*NHEADS*NTOK*HD];
__device__ __half g_v[(size_t)NB*NHEADS*NTOK*HD];
__device__ __half g_bm[(size_t)NWIN*NHEADS*NTOK*BMSTR];   // (bias+mask)*log2e, fp16
__device__ __half g_ao[(size_t)NB*NTOK*DIMC];

__device__ __forceinline__ void mma_f16(float* c, const unsigned* a, unsigned b0, unsigned b1) {
    asm volatile(
        "mma.sync.aligned.m16n8k16.row.col.f32.f16.f16.f32 "
        "{%0,%1,%2,%3}, {%4,%5,%6,%7}, {%8,%9}, {%0,%1,%2,%3};"
        : "+f"(c[0]), "+f"(c[1]), "+f"(c[2]), "+f"(c[3])
        : "r"(a[0]), "r"(a[1]), "r"(a[2]), "r"(a[3]), "r"(b0), "r"(b1));
}

__device__ __forceinline__ float ex2f(float x) {
    float r;
    asm("ex2.approx.ftz.f32 %0, %1;" : "=f"(r) : "f"(x));
    return r;
}

__device__ __forceinline__ unsigned ex2h2(float a, float b) {
    __half2 h = __floats2half2_rn(a, b);
    unsigned p = *(unsigned*)&h, r;
    asm("ex2.approx.f16x2 %0, %1;" : "=r"(r) : "r"(p));
    return r;
}

// ---------------------------------------------------------------------------
// Kernel 1: bm[(w*6+h)][i][j] = (bias+mask)*log2e as fp16, rows padded 352
// ---------------------------------------------------------------------------
__global__ void bm_kernel(const float* __restrict__ rpb, const float* __restrict__ mask)
{
    int i  = blockIdx.x;
    int wh = blockIdx.y;
    int w  = wh / NHEADS, h = wh - w * NHEADS;
    int di = i / 49, hi = (i / 7) % 7, wi = i % 7;
    __half* dst = g_bm + ((size_t)wh * NTOK + i) * BMSTR;
    const float* mrow = mask + ((size_t)w * NTOK + i) * NTOK;
    for (int j = threadIdx.x; j < BMSTR; j += 128) {
        float val = 0.f;
        if (j < NTOK) {
            int dj = j / 49, hj = (j / 7) % 7, wj = j % 7;
            int idx = (di - dj + 6) * 169 + (hi - hj + 6) * 13 + (wi - wj + 6);
            val = (rpb[idx * NHEADS + h] + mrow[j]) * LOG2E;
        }
        dst[j] = __float2half(val);
    }
}

// ---------------------------------------------------------------------------
// Kernel 2: fp16-MMA QKV GEMM; q scaled by SCALEF*log2e
// ---------------------------------------------------------------------------
__global__ __launch_bounds__(256) void qkv_gemm_f16(const float* __restrict__ X,
                                                    const float* __restrict__ W,
                                                    const float* __restrict__ bias)
{
    extern __shared__ __half gs[];
    __half* Xs = gs;                 // 128 x XSTR
    __half* Ws = gs + 128 * XSTR;    // 64  x XSTR
    int tid = threadIdx.x, lane = tid & 31, warp = tid >> 5;
    int gid = lane >> 2, qd = lane & 3;
    int m0 = blockIdx.y * 128, n0 = blockIdx.x * 64;
    int mrow = (warp & 3) * 32, ncol = (warp >> 2) * 32;

    for (int idx = tid; idx < 128 * 48; idx += 256) {
        int r = idx / 48, c4 = idx % 48;
        float4 v = *(const float4*)&X[(size_t)(m0 + r) * DIMC + c4 * 4];
        *(__half2*)&Xs[r * XSTR + c4 * 4]     = __floats2half2_rn(v.x, v.y);
        *(__half2*)&Xs[r * XSTR + c4 * 4 + 2] = __floats2half2_rn(v.z, v.w);
    }
    for (int idx = tid; idx < 64 * 48; idx += 256) {
        int r = idx / 48, c4 = idx % 48;
        float4 v = *(const float4*)&W[(size_t)(n0 + r) * DIMC + c4 * 4];
        *(__half2*)&Ws[r * XSTR + c4 * 4]     = __floats2half2_rn(v.x, v.y);
        *(__half2*)&Ws[r * XSTR + c4 * 4 + 2] = __floats2half2_rn(v.z, v.w);
    }
    __syncthreads();

    float c[2][4][4];
    #pragma unroll
    for (int mt = 0; mt < 2; mt++)
        #pragma unroll
        for (int nt = 0; nt < 4; nt++)
            #pragma unroll
            for (int i = 0; i < 4; i++) c[mt][nt][i] = 0.f;

    #pragma unroll
    for (int ks = 0; ks < 12; ks++) {
        int kk = ks * 16;
        unsigned a[2][4], bf[4][2];
        #pragma unroll
        for (int mt = 0; mt < 2; mt++) {
            int r = mrow + mt * 16 + gid;
            a[mt][0] = *(const unsigned*)&Xs[r * XSTR + kk + 2 * qd];
            a[mt][1] = *(const unsigned*)&Xs[(r + 8) * XSTR + kk + 2 * qd];
            a[mt][2] = *(const unsigned*)&Xs[r * XSTR + kk + 8 + 2 * qd];
            a[mt][3] = *(const unsigned*)&Xs[(r + 8) * XSTR + kk + 8 + 2 * qd];
        }
        #pragma unroll
        for (int nt = 0; nt < 4; nt++) {
            int rn = ncol + nt * 8 + gid;
            bf[nt][0] = *(const unsigned*)&Ws[rn * XSTR + kk + 2 * qd];
            bf[nt][1] = *(const unsigned*)&Ws[rn * XSTR + kk + 8 + 2 * qd];
        }
        #pragma unroll
        for (int mt = 0; mt < 2; mt++)
            #pragma unroll
            for (int nt = 0; nt < 4; nt++)
                mma_f16(c[mt][nt], a[mt], bf[nt][0], bf[nt][1]);
    }

    #pragma unroll
    for (int mt = 0; mt < 2; mt++) {
        int gmA = m0 + mrow + mt * 16 + gid, gmB = gmA + 8;
        int bA = gmA / NTOK, tA = gmA - bA * NTOK;
        int bB = gmB / NTOK, tB = gmB - bB * NTOK;
        #pragma unroll
        for (int nt = 0; nt < 4; nt++) {
            int gn = n0 + ncol + nt * 8 + 2 * qd;
            int sec = gn / DIMC, rem = gn - sec * DIMC;
            int hh = rem >> 5, dd = rem & 31;
            float b0 = bias[gn], b1 = bias[gn + 1];
            float vA0 = c[mt][nt][0] + b0, vA1 = c[mt][nt][1] + b1;
            float vB0 = c[mt][nt][2] + b0, vB1 = c[mt][nt][3] + b1;
            size_t offA = (((size_t)bA * NHEADS + hh) * NTOK + tA) * HD + dd;
            size_t offB = (((size_t)bB * NHEADS + hh) * NTOK + tB) * HD + dd;
            if (sec == 0) {
                *(__half2*)&g_q[offA] = __floats2half2_rn(vA0 * QSC, vA1 * QSC);
                *(__half2*)&g_q[offB] = __floats2half2_rn(vB0 * QSC, vB1 * QSC);
            } else if (sec == 1) {
                *(__half2*)&g_k[offA] = __floats2half2_rn(vA0, vA1);
                *(__half2*)&g_k[offB] = __floats2half2_rn(vB0, vB1);
            } else {
                *(__half2*)&g_v[offA] = __floats2half2_rn(vA0, vA1);
                *(__half2*)&g_v[offB] = __floats2half2_rn(vB0, vB1);
            }
        }
    }
}

// ---------------------------------------------------------------------------
// Kernel 3: fp16 flash attention; log2 softmax, lazy rescale (slack 3).
// ---------------------------------------------------------------------------
template<bool MASK>
__device__ __forceinline__ void attn_pair(int pr, int gid, int qd,
                                          const __half* __restrict__ Ks,
                                          const __half* __restrict__ Vt,
                                          const __half2 cur[4],
                                          const unsigned a[2][4], float occ[4][4],
                                          float& m0, float& m1, float& s0, float& s1)
{
    int kb0 = pr * 16;
    float c[2][4];
    #pragma unroll
    for (int sub = 0; sub < 2; sub++) {
        c[sub][0] = c[sub][1] = c[sub][2] = c[sub][3] = 0.f;
        int kb = kb0 + sub * 8;
        const __half* krow = &Ks[(kb + gid) * KSTRH + 2 * qd];
        #pragma unroll
        for (int ks = 0; ks < 2; ks++) {
            unsigned b0 = *(const unsigned*)&krow[ks * 16];
            unsigned b1 = *(const unsigned*)&krow[ks * 16 + 8];
            mma_f16(c[sub], a[ks], b0, b1);
        }
        float2 mA = __half22float2(cur[sub * 2]);
        float2 mB = __half22float2(cur[sub * 2 + 1]);
        c[sub][0] += mA.x; c[sub][1] += mA.y;
        c[sub][2] += mB.x; c[sub][3] += mB.y;
        if (MASK) {
            int k0 = kb + 2 * qd;
            if (k0 >= NTOK)     { c[sub][0] = -1e30f; c[sub][2] = -1e30f; }
            if (k0 + 1 >= NTOK) { c[sub][1] = -1e30f; c[sub][3] = -1e30f; }
        }
    }
    float cm0 = fmaxf(fmaxf(c[0][0], c[0][1]), fmaxf(c[1][0], c[1][1]));
    float cm1 = fmaxf(fmaxf(c[0][2], c[0][3]), fmaxf(c[1][2], c[1][3]));
    cm0 = fmaxf(cm0, __shfl_xor_sync(0xffffffffu, cm0, 1));
    cm0 = fmaxf(cm0, __shfl_xor_sync(0xffffffffu, cm0, 2));
    cm1 = fmaxf(cm1, __shfl_xor_sync(0xffffffffu, cm1, 1));
    cm1 = fmaxf(cm1, __shfl_xor_sync(0xffffffffu, cm1, 2));

    // lazy rescale: overshoot reference max by SLACK; update only when exceeded
    if (__any_sync(0xffffffffu, (cm0 > m0) || (cm1 > m1))) {
        float mn0 = (cm0 > m0) ? cm0 + SLACK : m0;
        float mn1 = (cm1 > m1) ? cm1 + SLACK : m1;
        float sc0 = ex2f(m0 - mn0), sc1 = ex2f(m1 - mn1);
        m0 = mn0; m1 = mn1;
        s0 *= sc0; s1 *= sc1;
        #pragma unroll
        for (int nh = 0; nh < 4; nh++) {
            occ[nh][0] *= sc0; occ[nh][1] *= sc0;
            occ[nh][2] *= sc1; occ[nh][3] *= sc1;
        }
    }

    unsigned pa[4];
    pa[0] = ex2h2(c[0][0] - m0, c[0][1] - m0);
    pa[1] = ex2h2(c[0][2] - m1, c[0][3] - m1);
    pa[2] = ex2h2(c[1][0] - m0, c[1][1] - m0);
    pa[3] = ex2h2(c[1][2] - m1, c[1][3] - m1);
    float2 f0 = __half22float2(*(__half2*)&pa[0]);
    float2 f2 = __half22float2(*(__half2*)&pa[2]);
    s0 += (f0.x + f0.y) + (f2.x + f2.y);
    float2 f1 = __half22float2(*(__half2*)&pa[1]);
    float2 f3 = __half22float2(*(__half2*)&pa[3]);
    s1 += (f1.x + f1.y) + (f3.x + f3.y);
    #pragma unroll
    for (int nh = 0; nh < 4; nh++) {
        const __half* vrow = &Vt[(nh * 8 + gid) * VTSTRH + kb0 + 2 * qd];
        unsigned b0 = *(const unsigned*)&vrow[0];
        unsigned b1 = *(const unsigned*)&vrow[8];
        mma_f16(occ[nh], pa, b0, b1);
    }
}

__global__ __launch_bounds__(512, 2) void attn_tc()
{
    extern __shared__ __half smh[];
    __half* Ks = smh;                      // 352*40 [key][hd]
    __half* Vt = Ks + 352 * KSTRH;         // 32*360 [hd][key]
    __half* Qs = Vt + 32 * VTSTRH;         // 352*40 [q][hd]

    int tid  = threadIdx.x;
    int h    = blockIdx.x;
    int by   = blockIdx.y;
    int b    = ((by & 3) << 6) | (by >> 2);    // L2-locality remap
    int w    = b & (NWIN - 1);
    int lane = tid & 31, warp = tid >> 5;
    int gid  = lane >> 2, qd = lane & 3;

    size_t base = (((size_t)b * NHEADS) + h) * NTOK * HD;
    const __half* qg = g_q + base;
    const __half* kg = g_k + base;
    const __half* vg = g_v + base;
    const __half* bm = g_bm + (size_t)(w * NHEADS + h) * NTOK * BMSTR;

    __half2 zero2 = __floats2half2_rn(0.f, 0.f);
    for (int i = tid; i < 352 * 16; i += 512) {
        int j = i >> 4, d2 = (i & 15) * 2;
        __half2 kv = zero2, vv = zero2;
        if (j < NTOK) {
            kv = *(const __half2*)&kg[j * HD + d2];
            vv = *(const __half2*)&vg[j * HD + d2];
        }
        *(__half2*)&Ks[j * KSTRH + d2] = kv;
        Vt[d2 * VTSTRH + j]       = __low2half(vv);
        Vt[(d2 + 1) * VTSTRH + j] = __high2half(vv);
        int t = j > NTOK - 1 ? NTOK - 1 : j;
        *(__half2*)&Qs[j * QSTRH + d2] = *(const __half2*)&qg[t * HD + d2];
    }
    __syncthreads();

    for (int wt = warp; wt < 22; wt += 16) {
        int r0 = wt * 16 + gid, r1 = r0 + 8;
        int tA = r0 > NTOK - 1 ? NTOK - 1 : r0;
        int tB = r1 > NTOK - 1 ? NTOK - 1 : r1;

        unsigned a[2][4];
        #pragma unroll
        for (int ks = 0; ks < 2; ks++) {
            a[ks][0] = *(const unsigned*)&Qs[r0 * QSTRH + ks * 16 + 2 * qd];
            a[ks][1] = *(const unsigned*)&Qs[r1 * QSTRH + ks * 16 + 2 * qd];
            a[ks][2] = *(const unsigned*)&Qs[r0 * QSTRH + ks * 16 + 8 + 2 * qd];
            a[ks][3] = *(const unsigned*)&Qs[r1 * QSTRH + ks * 16 + 8 + 2 * qd];
        }
        float occ[4][4];
        #pragma unroll
        for (int nh = 0; nh < 4; nh++)
            #pragma unroll
            for (int i = 0; i < 4; i++) occ[nh][i] = 0.f;
        float m0 = -1e30f, m1 = -1e30f, s0 = 0.f, s1 = 0.f;

        const __half* bmA = bm + (size_t)tA * BMSTR + 2 * qd;
        const __half* bmB = bm + (size_t)tB * BMSTR + 2 * qd;

        __half2 pf[4];
        pf[0] = *(const __half2*)&bmA[0];
        pf[1] = *(const __half2*)&bmB[0];
        pf[2] = *(const __half2*)&bmA[8];
        pf[3] = *(const __half2*)&bmB[8];

        #pragma unroll 1
        for (int pr = 0; pr < 21; pr++) {
            __half2 cur[4] = { pf[0], pf[1], pf[2], pf[3] };
            int nk = (pr + 1) * 16;
            pf[0] = *(const __half2*)&bmA[nk];
            pf[1] = *(const __half2*)&bmB[nk];
            pf[2] = *(const __half2*)&bmA[nk + 8];
            pf[3] = *(const __half2*)&bmB[nk + 8];
            attn_pair<false>(pr, gid, qd, Ks, Vt, cur, a, occ, m0, m1, s0, s1);
        }
        attn_pair<true>(21, gid, qd, Ks, Vt, pf, a, occ, m0, m1, s0, s1);

        s0 += __shfl_xor_sync(0xffffffffu, s0, 1);
        s0 += __shfl_xor_sync(0xffffffffu, s0, 2);
        s1 += __shfl_xor_sync(0xffffffffu, s1, 1);
        s1 += __shfl_xor_sync(0xffffffffu, s1, 2);
        float i0 = 1.f / s0, i1 = 1.f / s1;

        #pragma unroll
        for (int nh = 0; nh < 4; nh++) {
            int col = h * HD + nh * 8 + 2 * qd;
            if (r0 < NTOK)
                *(__half2*)&g_ao[((size_t)b * NTOK + r0) * DIMC + col] =
                    __floats2half2_rn(occ[nh][0] * i0, occ[nh][1] * i0);
            if (r1 < NTOK)
                *(__half2*)&g_ao[((size_t)b * NTOK + r1) * DIMC + col] =
                    __floats2half2_rn(occ[nh][2] * i1, occ[nh][3] * i1);
        }
    }
}

// ---------------------------------------------------------------------------
// Kernel 4: fp16-MMA projection GEMM.
// ---------------------------------------------------------------------------
__global__ __launch_bounds__(256) void proj_gemm_f16(const float* __restrict__ W,
                                                     const float* __restrict__ bias,
                                                     float* __restrict__ out)
{
    extern __shared__ __half gs[];
    __half* As = gs;                 // 128 x XSTR
    __half* Ws = gs + 128 * XSTR;    // 64  x XSTR
    int tid = threadIdx.x, lane = tid & 31, warp = tid >> 5;
    int gid = lane >> 2, qd = lane & 3;
    int m0 = blockIdx.y * 128, n0 = blockIdx.x * 64;
    int mrow = (warp & 3) * 32, ncol = (warp >> 2) * 32;

    for (int idx = tid; idx < 128 * 48; idx += 256) {
        int r = idx / 48, c4 = idx % 48;
        uint2 v = *(const uint2*)&g_ao[(size_t)(m0 + r) * DIMC + c4 * 4];
        *(uint2*)&As[r * XSTR + c4 * 4] = v;
    }
    for (int idx = tid; idx < 64 * 48; idx += 256) {
        int r = idx / 48, c4 = idx % 48;
        float4 v = *(const float4*)&W[(size_t)(n0 + r) * DIMC + c4 * 4];
        *(__half2*)&Ws[r * XSTR + c4 * 4]     = __floats2half2_rn(v.x, v.y);
        *(__half2*)&Ws[r * XSTR + c4 * 4 + 2] = __floats2half2_rn(v.z, v.w);
    }
    __syncthreads();

    float c[2][4][4];
    #pragma unroll
    for (int mt = 0; mt < 2; mt++)
        #pragma unroll
        for (int nt = 0; nt < 4; nt++)
            #pragma unroll
            for (int i = 0; i < 4; i++) c[mt][nt][i] = 0.f;

    #pragma unroll
    for (int ks = 0; ks < 12; ks++) {
        int kk = ks * 16;
        unsigned a[2][4], bf[4][2];
        #pragma unroll
        for (int mt = 0; mt < 2; mt++) {
            int r = mrow + mt * 16 + gid;
            a[mt][0] = *(const unsigned*)&As[r * XSTR + kk + 2 * qd];
            a[mt][1] = *(const unsigned*)&As[(r + 8) * XSTR + kk + 2 * qd];
            a[mt][2] = *(const unsigned*)&As[r * XSTR + kk + 8 + 2 * qd];
            a[mt][3] = *(const unsigned*)&As[(r + 8) * XSTR + kk + 8 + 2 * qd];
        }
        #pragma unroll
        for (int nt = 0; nt < 4; nt++) {
            int rn = ncol + nt * 8 + gid;
            bf[nt][0] = *(const unsigned*)&Ws[rn * XSTR + kk + 2 * qd];
            bf[nt][1] = *(const unsigned*)&Ws[rn * XSTR + kk + 8 + 2 * qd];
        }
        #pragma unroll
        for (int mt = 0; mt < 2; mt++)
            #pragma unroll
            for (int nt = 0; nt < 4; nt++)
                mma_f16(c[mt][nt], a[mt], bf[nt][0], bf[nt][1]);
    }

    #pragma unroll
    for (int mt = 0; mt < 2; mt++) {
        int gmA = m0 + mrow + mt * 16 + gid, gmB = gmA + 8;
        #pragma unroll
        for (int nt = 0; nt < 4; nt++) {
            int gn = n0 + ncol + nt * 8 + 2 * qd;
            float b0 = bias[gn], b1 = bias[gn + 1];
            *(float2*)&out[(size_t)gmA * DIMC + gn] =
                make_float2(c[mt][nt][0] + b0, c[mt][nt][1] + b1);
            *(float2*)&out[(size_t)gmB * DIMC + gn] =
                make_float2(c[mt][nt][2] + b0, c[mt][nt][3] + b1);
        }
    }
}

// ---------------------------------------------------------------------------
extern "C" void kernel_launch(void* const* d_in, const int* in_sizes, int n_in,
                              void* d_out, int out_size)
{
    const float* x      = (const float*)d_in[0];
    const float* mask   = (const float*)d_in[1];
    const float* qkv_w  = (const float*)d_in[2];
    const float* qkv_b  = (const float*)d_in[3];
    const float* rpb    = (const float*)d_in[4];
    const float* proj_w = (const float*)d_in[5];
    const float* proj_b = (const float*)d_in[6];
    float* out = (float*)d_out;

    (void)in_sizes; (void)n_in; (void)out_size;

    int smem_attn = (352 * KSTRH + 32 * VTSTRH + 352 * QSTRH) * (int)sizeof(__half);
    int smem_gemm = 192 * XSTR * (int)sizeof(__half);
    cudaFuncSetAttribute(attn_tc, cudaFuncAttributeMaxDynamicSharedMemorySize, smem_attn);
    cudaFuncSetAttribute(qkv_gemm_f16, cudaFuncAttributeMaxDynamicSharedMemorySize, smem_gemm);
    cudaFuncSetAttribute(proj_gemm_f16, cudaFuncAttributeMaxDynamicSharedMemorySize, smem_gemm);

    bm_kernel<<<dim3(NTOK, NWIN * NHEADS), 128>>>(rpb, mask);
    qkv_gemm_f16<<<dim3(QKVN / 64, MROWS / 128), 256, smem_gemm>>>(x, qkv_w, qkv_b);
    attn_tc<<<dim3(NHEADS, NB), 512, smem_attn>>>();
    proj_gemm_f16<<<dim3(DIMC / 64, MROWS / 128), 256, smem_gemm>>>(proj_w, proj_b, out);
}